// round 1
// baseline (speedup 1.0000x reference)
#include <cuda_runtime.h>

#define BB 128
#define TT 1024
#define DD 128
#define CC 384          // 3*D
#define SEG 8           // mean partial segments
#define TSEG (TT/SEG)   // 128 rows per partial
#define TM 32           // rows per block in main kernel

// scratch for partial means (fully overwritten every launch -> deterministic)
__device__ float g_partial[BB * SEG * DD];

// ---------------------------------------------------------------------------
// Kernel 1: partial sums of y over T segments. grid = B*SEG, block = 128.
// ---------------------------------------------------------------------------
__global__ void mean_partial_kernel(const float* __restrict__ x) {
    int bs = blockIdx.x;            // b*SEG + s
    int b  = bs / SEG;
    int s  = bs % SEG;
    int d  = threadIdx.x;           // 0..127
    const float* p = x + ((size_t)(b * TT + s * TSEG)) * CC + d;
    float acc = 0.f;
#pragma unroll 8
    for (int t = 0; t < TSEG; ++t)
        acc += p[(size_t)t * CC];
    g_partial[bs * DD + d] = acc;
}

// ---------------------------------------------------------------------------
// Kernel 2: main fused kernel. grid = B*(T/TM), block = 256 threads.
// smem: K [128x128] (64KB) + V [32x128] (16KB) + mean [128]
// ---------------------------------------------------------------------------
__global__ __launch_bounds__(256) void crosschan_main_kernel(
    const float* __restrict__ x,
    const float* __restrict__ kern,
    float* __restrict__ out)
{
    extern __shared__ float smem[];
    float* Ks = smem;                 // [128*128]
    float* Vs = smem + DD * DD;       // [TM*128]
    float* Ms = Vs + TM * DD;         // [128]

    const int bx  = blockIdx.x;
    const int b   = bx >> 5;          // T/TM == 32
    const int tt  = bx & 31;
    const int tid = threadIdx.x;

    // ---- load kernel matrix into smem (row-major K[d][j]) ----
    {
        const float4* kg = (const float4*)kern;
        float4* ks4 = (float4*)Ks;
#pragma unroll
        for (int i = tid; i < DD * DD / 4; i += 256)
            ks4[i] = kg[i];
    }
    // ---- reduce partial means ----
    if (tid < DD) {
        float m = 0.f;
#pragma unroll
        for (int s = 0; s < SEG; ++s)
            m += g_partial[(b * SEG + s) * DD + tid];
        Ms[tid] = m * (1.0f / (float)TT);
    }
    __syncthreads();

    // ------------------------------------------------------------------
    // Phase 1: per-row softmax + intensity + v = sm*(y-mean) into smem.
    // 32 groups of 8 threads; group g owns row g; lane l owns d = l*16..+15
    // ------------------------------------------------------------------
    {
        const int g = tid >> 3;       // row within tile (0..31)
        const int l = tid & 7;        // lane within row group
        const int t = tt * TM + g;
        const size_t rowbase = ((size_t)(b * TT + t)) * CC;
        const float4* xr = (const float4*)(x + rowbase);    // 96 float4 per row
        float4* o4 = (float4*)(out + rowbase);

        float4 w4[4], y4[4];
#pragma unroll
        for (int i = 0; i < 4; ++i) {
            w4[i] = xr[32 + l * 4 + i];   // w channels [128,256)
            y4[i] = xr[l * 4 + i];        // y channels [0,128)
        }
        float ex[16];
        float s = 0.f;
#pragma unroll
        for (int i = 0; i < 4; ++i) {
            ex[4*i+0] = __expf(w4[i].x);
            ex[4*i+1] = __expf(w4[i].y);
            ex[4*i+2] = __expf(w4[i].z);
            ex[4*i+3] = __expf(w4[i].w);
            s += ex[4*i+0] + ex[4*i+1] + ex[4*i+2] + ex[4*i+3];
        }
        // reduce sum over the 8 contiguous lanes of this group
        s += __shfl_xor_sync(0xffffffffu, s, 1);
        s += __shfl_xor_sync(0xffffffffu, s, 2);
        s += __shfl_xor_sync(0xffffffffu, s, 4);
        const float inv = 1.0f / s;

#pragma unroll
        for (int i = 0; i < 4; ++i) {
            const int d0 = l * 16 + i * 4;
            float4 ev = make_float4(ex[4*i+0], ex[4*i+1], ex[4*i+2], ex[4*i+3]);
            // intensity = exp(w) -> channels [128,256)
            o4[32 + l * 4 + i] = ev;
            float4 vv;
            vv.x = ev.x * inv * (y4[i].x - Ms[d0 + 0]);
            vv.y = ev.y * inv * (y4[i].y - Ms[d0 + 1]);
            vv.z = ev.z * inv * (y4[i].z - Ms[d0 + 2]);
            vv.w = ev.w * inv * (y4[i].w - Ms[d0 + 3]);
            *(float4*)&Vs[g * DD + d0] = vv;
        }
    }
    __syncthreads();

    // ------------------------------------------------------------------
    // Phase 2: GEMM  smooth[r][c] = sum_d V[r][d] * K[d][c]
    // thread (tx=tid%32, ty=tid/32): rows ty*4..+3, cols tx*4..+3
    // per d: V loads are warp-uniform broadcasts, K load is float4.
    // ------------------------------------------------------------------
    const int tx = tid & 31;
    const int ty = tid >> 5;
    const int r0 = ty * 4;
    const int c0 = tx << 2;

    float acc[4][4];
#pragma unroll
    for (int i = 0; i < 4; ++i)
#pragma unroll
        for (int j = 0; j < 4; ++j)
            acc[i][j] = 0.f;

#pragma unroll 4
    for (int d0 = 0; d0 < DD; d0 += 4) {
        float4 va[4];
#pragma unroll
        for (int i = 0; i < 4; ++i)
            va[i] = *(const float4*)&Vs[(r0 + i) * DD + d0];
#pragma unroll
        for (int dd = 0; dd < 4; ++dd) {
            float4 kk = *(const float4*)&Ks[(d0 + dd) * DD + c0];
            float v0 = ((const float*)&va[0])[dd];
            float v1 = ((const float*)&va[1])[dd];
            float v2 = ((const float*)&va[2])[dd];
            float v3 = ((const float*)&va[3])[dd];
            acc[0][0] += v0 * kk.x; acc[0][1] += v0 * kk.y; acc[0][2] += v0 * kk.z; acc[0][3] += v0 * kk.w;
            acc[1][0] += v1 * kk.x; acc[1][1] += v1 * kk.y; acc[1][2] += v1 * kk.z; acc[1][3] += v1 * kk.w;
            acc[2][0] += v2 * kk.x; acc[2][1] += v2 * kk.y; acc[2][2] += v2 * kk.z; acc[2][3] += v2 * kk.w;
            acc[3][0] += v3 * kk.x; acc[3][1] += v3 * kk.y; acc[3][2] += v3 * kk.z; acc[3][3] += v3 * kk.w;
        }
    }

    // ------------------------------------------------------------------
    // Phase 3: epilogue. smooth = acc + mean; y_trans = y_obs - smooth.
    // ------------------------------------------------------------------
    const float4 mm = *(const float4*)&Ms[c0];
#pragma unroll
    for (int i = 0; i < 4; ++i) {
        const int t2 = tt * TM + r0 + i;
        const size_t base = ((size_t)(b * TT + t2)) * CC;
        float4 sm4 = make_float4(acc[i][0] + mm.x, acc[i][1] + mm.y,
                                 acc[i][2] + mm.z, acc[i][3] + mm.w);
        *(float4*)(out + base + c0) = sm4;                       // smooth: [0,128)
        float4 yo = *(const float4*)(x + base + 2 * DD + c0);    // y_obs: [256,384)
        float4 yt = make_float4(yo.x - sm4.x, yo.y - sm4.y,
                                yo.z - sm4.z, yo.w - sm4.w);
        *(float4*)(out + base + 2 * DD + c0) = yt;               // y_trans: [256,384)
    }
}

// ---------------------------------------------------------------------------
extern "C" void kernel_launch(void* const* d_in, const int* in_sizes, int n_in,
                              void* d_out, int out_size) {
    const float* x    = (const float*)d_in[0];
    const float* kern = (const float*)d_in[1];
    float* out        = (float*)d_out;

    mean_partial_kernel<<<BB * SEG, DD>>>(x);

    const size_t smem = (size_t)(DD * DD + TM * DD + DD) * sizeof(float);
    cudaFuncSetAttribute(crosschan_main_kernel,
                         cudaFuncAttributeMaxDynamicSharedMemorySize, (int)smem);
    crosschan_main_kernel<<<BB * (TT / TM), 256, smem>>>(x, kern, out);
}

// round 3
// speedup vs baseline: 1.6784x; 1.6784x over previous
#include <cuda_runtime.h>
#include <cuda_bf16.h>
#include <cstdint>

#define BB 128
#define TT 1024
#define DD 128
#define CC 384
#define SEG 8
#define TSEG (TT/SEG)
#define TILE 64                   // rows per CTA

// ---- smem byte offsets ----
#define S_MS 0                    // 512 B mean
#define S_E  512                  // 32 KB  E = kern - I, bf16 [n][k] swizzled
#define S_A  (S_E + 32768)        // 16 KB  A = bf16(V)    [m][k] swizzled
#define S_V  (S_A + 16384)        // 64 x 132 fp32 = 33792 B (aliased as D)
#define S_TOTAL (S_V + TILE * 132 * 4)

// ---- device scratch (fully overwritten each launch -> deterministic) ----
__device__ float g_partial[BB * SEG * DD];
__device__ __align__(16) unsigned char g_E[32768];

// swizzled offset inside a [rows][128] bf16 tile with 256B rows:
// 16B chunk index (k>>3) XOR'd with (row&7)
__device__ __forceinline__ uint32_t tile_off(int r, int k) {
    return (uint32_t)r * 256u + ((((uint32_t)k >> 3) ^ ((uint32_t)r & 7u)) << 4)
         + ((uint32_t)k & 7u) * 2u;
}

__device__ __forceinline__ uint32_t smem_u32(const void* p) {
    uint32_t a;
    asm("{ .reg .u64 t; cvta.to.shared.u64 t, %1; cvt.u32.u64 %0, t; }"
        : "=r"(a) : "l"(p));
    return a;
}

#define LDMATRIX_X4(r0, r1, r2, r3, addr)                                      \
    asm volatile("ldmatrix.sync.aligned.m8n8.x4.shared.b16 {%0,%1,%2,%3}, [%4];" \
        : "=r"(r0), "=r"(r1), "=r"(r2), "=r"(r3) : "r"(addr))

#define MMA_BF16(d, a0, a1, a2, a3, b0, b1)                                    \
    asm volatile("mma.sync.aligned.m16n8k16.row.col.f32.bf16.bf16.f32 "        \
        "{%0,%1,%2,%3}, {%4,%5,%6,%7}, {%8,%9}, {%0,%1,%2,%3};"                \
        : "+f"((d)[0]), "+f"((d)[1]), "+f"((d)[2]), "+f"((d)[3])               \
        : "r"(a0), "r"(a1), "r"(a2), "r"(a3), "r"(b0), "r"(b1))

// ---------------------------------------------------------------------------
// Kernel 0: E[n][k] = kern[k*128 + n] - (n==k), bf16, swizzled tile layout
// ---------------------------------------------------------------------------
__global__ void setup_E_kernel(const float* __restrict__ kern) {
    int idx = blockIdx.x * blockDim.x + threadIdx.x;   // 16384
    int n = idx >> 7, k = idx & 127;
    float v = kern[k * DD + n] - (n == k ? 1.0f : 0.0f);
    *(__nv_bfloat16*)(g_E + tile_off(n, k)) = __float2bfloat16(v);
}

// ---------------------------------------------------------------------------
// Kernel 1: partial sums of y over T segments
// ---------------------------------------------------------------------------
__global__ void mean_partial_kernel(const float* __restrict__ x) {
    int bs = blockIdx.x;
    int b = bs / SEG, s = bs % SEG, d = threadIdx.x;
    const float* p = x + ((size_t)(b * TT + s * TSEG)) * CC + d;
    float acc = 0.f;
#pragma unroll 8
    for (int t = 0; t < TSEG; ++t) acc += p[(size_t)t * CC];
    g_partial[bs * DD + d] = acc;
}

// ---------------------------------------------------------------------------
// Kernel 2: main fused kernel. grid = 2048 (64 rows each), block = 256.
// smooth = V + V@E + mean, V = softmax(w)*(y-mean), all fused.
// ---------------------------------------------------------------------------
__global__ __launch_bounds__(256, 2)
void crosschan_main_kernel(const float* __restrict__ x, float* __restrict__ out)
{
    extern __shared__ char smem[];
    const uint32_t sbase = smem_u32(smem);
    float* Ms = (float*)(smem + S_MS);
    float* Vs = (float*)(smem + S_V);       // [64][132] fp32, aliased as D
    const int tid  = threadIdx.x;
    const int wid  = tid >> 5;
    const int lane = tid & 31;
    const int b    = blockIdx.x >> 4;       // 16 tiles of 64 rows per batch

    // mean reduce (128 threads)
    if (tid < DD) {
        float m = 0.f;
#pragma unroll
        for (int s = 0; s < SEG; ++s) m += g_partial[(b * SEG + s) * DD + tid];
        Ms[tid] = m * (1.0f / (float)TT);
    }
    // copy E tile into smem (L2-hot, already in MMA layout)
    {
        const float4* eg = (const float4*)g_E;
        float4* es = (float4*)(smem + S_E);
#pragma unroll
        for (int i = tid; i < 2048; i += 256) es[i] = eg[i];
    }
    __syncthreads();

    // ------------------------------------------------------------------
    // Phase 1: softmax + intensity + V (fp32 smem) + bf16(V) (A tile)
    // 8 threads per row, 32 rows per pass, 2 passes.
    // ------------------------------------------------------------------
    {
        const int l = tid & 7;
#pragma unroll
        for (int pass = 0; pass < 2; ++pass) {
            const int r = pass * 32 + (tid >> 3);
            const size_t rowbase = ((size_t)(blockIdx.x * TILE + r)) * CC;
            const float4* xr = (const float4*)(x + rowbase);
            float4* o4 = (float4*)(out + rowbase);

            float4 w4[4], y4[4];
#pragma unroll
            for (int i = 0; i < 4; ++i) {
                y4[i] = xr[l * 4 + i];
                w4[i] = xr[32 + l * 4 + i];
            }
            float ex[16], s = 0.f;
#pragma unroll
            for (int i = 0; i < 4; ++i) {
                ex[4*i+0] = __expf(w4[i].x); ex[4*i+1] = __expf(w4[i].y);
                ex[4*i+2] = __expf(w4[i].z); ex[4*i+3] = __expf(w4[i].w);
                s += ex[4*i+0] + ex[4*i+1] + ex[4*i+2] + ex[4*i+3];
            }
            s += __shfl_xor_sync(0xffffffffu, s, 1);
            s += __shfl_xor_sync(0xffffffffu, s, 2);
            s += __shfl_xor_sync(0xffffffffu, s, 4);
            const float inv = 1.0f / s;

            float v[16];
#pragma unroll
            for (int i = 0; i < 4; ++i) {
                const int c0 = l * 16 + i * 4;
                float4 ev = make_float4(ex[4*i+0], ex[4*i+1], ex[4*i+2], ex[4*i+3]);
                o4[32 + l * 4 + i] = ev;   // intensity = exp(w)
                v[4*i+0] = ev.x * inv * (y4[i].x - Ms[c0 + 0]);
                v[4*i+1] = ev.y * inv * (y4[i].y - Ms[c0 + 1]);
                v[4*i+2] = ev.z * inv * (y4[i].z - Ms[c0 + 2]);
                v[4*i+3] = ev.w * inv * (y4[i].w - Ms[c0 + 3]);
                *(float4*)&Vs[r * 132 + c0] =
                    make_float4(v[4*i+0], v[4*i+1], v[4*i+2], v[4*i+3]);
            }
            // bf16(V) -> A tile, two 16B chunks (8 bf16 each)
#pragma unroll
            for (int h = 0; h < 2; ++h) {
                uint32_t p4[4];
#pragma unroll
                for (int j = 0; j < 4; ++j) {
                    __nv_bfloat162 t = __floats2bfloat162_rn(v[h*8 + 2*j],
                                                             v[h*8 + 2*j + 1]);
                    p4[j] = *reinterpret_cast<uint32_t*>(&t);
                }
                *(uint4*)(smem + S_A + tile_off(r, l * 16 + h * 8)) =
                    make_uint4(p4[0], p4[1], p4[2], p4[3]);
            }
        }
    }
    __syncthreads();

    // ------------------------------------------------------------------
    // Phase 2: V@E via bf16 mma.sync. Warp w: rows m0..m0+15, cols nb..nb+63.
    // ------------------------------------------------------------------
    const int m0 = (wid >> 1) * 16;
    const int nb = (wid & 1) * 64;

    float acc[8][4];
#pragma unroll
    for (int i = 0; i < 8; ++i)
#pragma unroll
        for (int j = 0; j < 4; ++j) acc[i][j] = 0.f;

    // per-lane ldmatrix base addresses
    const int aRow = m0 + (lane & 7) + (lane & 8);
    const uint32_t aBase = sbase + S_A + aRow * 256;
    const uint32_t aXor  = (uint32_t)(aRow & 7) << 4;
    const uint32_t aSel  = (uint32_t)(lane >> 4);       // chunk +0/+1
    const int bRowOff = (lane & 7) + ((lane >> 4) << 3); // n within 16
    const uint32_t bSel = (uint32_t)((lane >> 3) & 1);

#pragma unroll
    for (int ks = 0; ks < 8; ++ks) {
        uint32_t a0, a1, a2, a3;
        LDMATRIX_X4(a0, a1, a2, a3,
                    aBase + ((((2u * ks + aSel) << 4) ^ aXor)));
#pragma unroll
        for (int nt2 = 0; nt2 < 4; ++nt2) {
            const int n0 = nb + nt2 * 16;
            const int bRow = n0 + bRowOff;
            uint32_t baddr = sbase + S_E + bRow * 256
                           + ((((2u * ks + bSel) << 4) ^ ((uint32_t)(bRow & 7) << 4)));
            uint32_t b0, b1, b2, b3;
            LDMATRIX_X4(b0, b1, b2, b3, baddr);
            MMA_BF16(acc[nt2 * 2],     a0, a1, a2, a3, b0, b1);
            MMA_BF16(acc[nt2 * 2 + 1], a0, a1, a2, a3, b2, b3);
        }
    }

    // ------------------------------------------------------------------
    // Phase 3a: fold D = acc + V + mean back into Vs (same addresses)
    // ------------------------------------------------------------------
    {
        const int r1 = m0 + (lane >> 2);
        const int r2 = r1 + 8;
        const int cl = 2 * (lane & 3);
#pragma unroll
        for (int nt = 0; nt < 8; ++nt) {
            const int c = nb + nt * 8 + cl;
            const float m_c0 = Ms[c], m_c1 = Ms[c + 1];
            float* p1 = &Vs[r1 * 132 + c];
            float* p2 = &Vs[r2 * 132 + c];
            float d00 = acc[nt][0] + p1[0] + m_c0;
            float d01 = acc[nt][1] + p1[1] + m_c1;
            float d10 = acc[nt][2] + p2[0] + m_c0;
            float d11 = acc[nt][3] + p2[1] + m_c1;
            p1[0] = d00; p1[1] = d01;
            p2[0] = d10; p2[1] = d11;
        }
    }
    __syncthreads();

    // ------------------------------------------------------------------
    // Phase 3b: coalesced epilogue: smooth = D; y_trans = y_obs - smooth
    // ------------------------------------------------------------------
    {
        const int J = lane;   // float4 column 0..31
#pragma unroll
        for (int it = 0; it < 8; ++it) {
            const int r = it * 8 + wid;
            float4 d4 = *(const float4*)&Vs[r * 132 + J * 4];
            const size_t base = ((size_t)(blockIdx.x * TILE + r)) * CC;
            ((float4*)(out + base))[J] = d4;                      // smooth
            float4 yo = ((const float4*)(x + base + 2 * DD))[J];  // y_obs
            ((float4*)(out + base + 2 * DD))[J] =
                make_float4(yo.x - d4.x, yo.y - d4.y, yo.z - d4.z, yo.w - d4.w);
        }
    }
}

// ---------------------------------------------------------------------------
extern "C" void kernel_launch(void* const* d_in, const int* in_sizes, int n_in,
                              void* d_out, int out_size) {
    const float* x    = (const float*)d_in[0];
    const float* kern = (const float*)d_in[1];
    float* out        = (float*)d_out;

    setup_E_kernel<<<128, 128>>>(kern);
    mean_partial_kernel<<<BB * SEG, DD>>>(x);

    cudaFuncSetAttribute(crosschan_main_kernel,
                         cudaFuncAttributeMaxDynamicSharedMemorySize, S_TOTAL);
    crosschan_main_kernel<<<BB * (TT / TILE), 256, S_TOTAL>>>(x, out);
}

// round 4
// speedup vs baseline: 1.7433x; 1.0386x over previous
#include <cuda_runtime.h>
#include <cuda_bf16.h>
#include <cstdint>

#define BB 128
#define TT 1024
#define DD 128
#define CC 384
#define SEG 8
#define TSEG (TT/SEG)
#define TILE 64                   // rows per CTA

// ---- smem byte offsets ----
#define S_MS 0                    // 512 B mean
#define S_E  512                  // 32 KB  E = kern - I, bf16 [n][k] swizzled
#define S_A  (S_E + 32768)        // 16 KB  A = bf16(V)    [m][k] swizzled
#define S_V  (S_A + 16384)        // 64 x 132 fp32 = 33792 B
#define S_TOTAL (S_V + TILE * 132 * 4)

// ---- device scratch (fully overwritten each launch -> deterministic) ----
__device__ float g_partial[BB * SEG * DD];
__device__ __align__(16) unsigned char g_E[32768];

// swizzled offset inside a [rows][128] bf16 tile with 256B rows
__device__ __forceinline__ uint32_t tile_off(int r, int k) {
    return (uint32_t)r * 256u + ((((uint32_t)k >> 3) ^ ((uint32_t)r & 7u)) << 4)
         + ((uint32_t)k & 7u) * 2u;
}

__device__ __forceinline__ uint32_t smem_u32(const void* p) {
    uint32_t a;
    asm("{ .reg .u64 t; cvta.to.shared.u64 t, %1; cvt.u32.u64 %0, t; }"
        : "=r"(a) : "l"(p));
    return a;
}

#define LDMATRIX_X4(r0, r1, r2, r3, addr)                                      \
    asm volatile("ldmatrix.sync.aligned.m8n8.x4.shared.b16 {%0,%1,%2,%3}, [%4];" \
        : "=r"(r0), "=r"(r1), "=r"(r2), "=r"(r3) : "r"(addr))

#define MMA_BF16(d, a0, a1, a2, a3, b0, b1)                                    \
    asm volatile("mma.sync.aligned.m16n8k16.row.col.f32.bf16.bf16.f32 "        \
        "{%0,%1,%2,%3}, {%4,%5,%6,%7}, {%8,%9}, {%0,%1,%2,%3};"                \
        : "+f"((d)[0]), "+f"((d)[1]), "+f"((d)[2]), "+f"((d)[3])               \
        : "r"(a0), "r"(a1), "r"(a2), "r"(a3), "r"(b0), "r"(b1))

#define CP_ASYNC16(saddr, gaddr)                                               \
    asm volatile("cp.async.cg.shared.global [%0], [%1], 16;"                   \
        :: "r"(saddr), "l"(gaddr) : "memory")
#define CP_COMMIT() asm volatile("cp.async.commit_group;" ::: "memory")
#define CP_WAIT0()  asm volatile("cp.async.wait_group 0;" ::: "memory")

// ---------------------------------------------------------------------------
// Kernel A: fused prep. blocks [0,1024) = mean partials; [1024,1152) = E setup
// ---------------------------------------------------------------------------
__global__ void prep_kernel(const float* __restrict__ x,
                            const float* __restrict__ kern) {
    if (blockIdx.x < BB * SEG) {
        int bs = blockIdx.x;
        int b = bs / SEG, s = bs % SEG, d = threadIdx.x;
        const float* p = x + ((size_t)(b * TT + s * TSEG)) * CC + d;
        float acc = 0.f;
#pragma unroll 8
        for (int t = 0; t < TSEG; ++t) acc += p[(size_t)t * CC];
        g_partial[bs * DD + d] = acc;
    } else {
        int idx = (blockIdx.x - BB * SEG) * 128 + threadIdx.x;   // 16384
        int n = idx >> 7, k = idx & 127;
        float v = kern[k * DD + n] - (n == k ? 1.0f : 0.0f);
        *(__nv_bfloat16*)(g_E + tile_off(n, k)) = __float2bfloat16(v);
    }
}

// ---------------------------------------------------------------------------
// Kernel B: main fused kernel. grid = 2048 (64 rows each), block = 256.
// smooth = V + V@E + mean, V = softmax(w)*(y-mean), all fused.
// ---------------------------------------------------------------------------
__global__ __launch_bounds__(256, 2)
void crosschan_main_kernel(const float* __restrict__ x, float* __restrict__ out)
{
    extern __shared__ char smem[];
    const uint32_t sbase = smem_u32(smem);
    float* Ms = (float*)(smem + S_MS);
    float* Vs = (float*)(smem + S_V);       // [64][132] fp32
    const int tid  = threadIdx.x;
    const int wid  = tid >> 5;
    const int lane = tid & 31;
    const int b    = blockIdx.x >> 4;       // 16 tiles of 64 rows per batch

    // async E copy: issue now, wait after phase 1
    {
        const char* eg = (const char*)g_E;
#pragma unroll
        for (int i = 0; i < 8; ++i) {
            uint32_t off = (uint32_t)(tid + i * 256) * 16u;
            CP_ASYNC16(sbase + S_E + off, eg + off);
        }
        CP_COMMIT();
    }

    // mean reduce (128 threads)
    if (tid < DD) {
        float m = 0.f;
#pragma unroll
        for (int s = 0; s < SEG; ++s) m += g_partial[(b * SEG + s) * DD + tid];
        Ms[tid] = m * (1.0f / (float)TT);
    }
    __syncthreads();

    // ------------------------------------------------------------------
    // Phase 1: softmax + intensity + V (fp32 smem) + bf16(V) (A tile)
    // ------------------------------------------------------------------
    {
        const int l = tid & 7;
#pragma unroll
        for (int pass = 0; pass < 2; ++pass) {
            const int r = pass * 32 + (tid >> 3);
            const size_t rowbase = ((size_t)(blockIdx.x * TILE + r)) * CC;
            const float4* xr = (const float4*)(x + rowbase);
            float4* o4 = (float4*)(out + rowbase);

            float4 w4[4], y4[4];
#pragma unroll
            for (int i = 0; i < 4; ++i) {
                y4[i] = xr[l * 4 + i];
                w4[i] = xr[32 + l * 4 + i];
            }
            float ex[16], s = 0.f;
#pragma unroll
            for (int i = 0; i < 4; ++i) {
                ex[4*i+0] = __expf(w4[i].x); ex[4*i+1] = __expf(w4[i].y);
                ex[4*i+2] = __expf(w4[i].z); ex[4*i+3] = __expf(w4[i].w);
                s += ex[4*i+0] + ex[4*i+1] + ex[4*i+2] + ex[4*i+3];
            }
            s += __shfl_xor_sync(0xffffffffu, s, 1);
            s += __shfl_xor_sync(0xffffffffu, s, 2);
            s += __shfl_xor_sync(0xffffffffu, s, 4);
            const float inv = 1.0f / s;

            float v[16];
#pragma unroll
            for (int i = 0; i < 4; ++i) {
                const int c0 = l * 16 + i * 4;
                float4 ev = make_float4(ex[4*i+0], ex[4*i+1], ex[4*i+2], ex[4*i+3]);
                o4[32 + l * 4 + i] = ev;   // intensity = exp(w)
                v[4*i+0] = ev.x * inv * (y4[i].x - Ms[c0 + 0]);
                v[4*i+1] = ev.y * inv * (y4[i].y - Ms[c0 + 1]);
                v[4*i+2] = ev.z * inv * (y4[i].z - Ms[c0 + 2]);
                v[4*i+3] = ev.w * inv * (y4[i].w - Ms[c0 + 3]);
                *(float4*)&Vs[r * 132 + c0] =
                    make_float4(v[4*i+0], v[4*i+1], v[4*i+2], v[4*i+3]);
            }
#pragma unroll
            for (int h = 0; h < 2; ++h) {
                uint32_t p4[4];
#pragma unroll
                for (int j = 0; j < 4; ++j) {
                    __nv_bfloat162 t = __floats2bfloat162_rn(v[h*8 + 2*j],
                                                             v[h*8 + 2*j + 1]);
                    p4[j] = *reinterpret_cast<uint32_t*>(&t);
                }
                *(uint4*)(smem + S_A + tile_off(r, l * 16 + h * 8)) =
                    make_uint4(p4[0], p4[1], p4[2], p4[3]);
            }
        }
    }
    CP_WAIT0();
    __syncthreads();

    // ------------------------------------------------------------------
    // Phase 2: V@E via bf16 mma.sync. Warp w: rows m0..m0+15, cols nb..nb+63.
    // ------------------------------------------------------------------
    const int m0 = (wid >> 1) * 16;
    const int nb = (wid & 1) * 64;

    float acc[8][4];
#pragma unroll
    for (int i = 0; i < 8; ++i)
#pragma unroll
        for (int j = 0; j < 4; ++j) acc[i][j] = 0.f;

    const int aRow = m0 + (lane & 7) + (lane & 8);
    const uint32_t aBase = sbase + S_A + aRow * 256;
    const uint32_t aXor  = (uint32_t)(aRow & 7) << 4;
    const uint32_t aSel  = (uint32_t)(lane >> 4);
    const int bRowOff = (lane & 7) + ((lane >> 4) << 3);
    const uint32_t bSel = (uint32_t)((lane >> 3) & 1);

#pragma unroll
    for (int ks = 0; ks < 8; ++ks) {
        uint32_t a0, a1, a2, a3;
        LDMATRIX_X4(a0, a1, a2, a3,
                    aBase + ((((2u * ks + aSel) << 4) ^ aXor)));
#pragma unroll
        for (int nt2 = 0; nt2 < 4; ++nt2) {
            const int n0 = nb + nt2 * 16;
            const int bRow = n0 + bRowOff;
            uint32_t baddr = sbase + S_E + bRow * 256
                           + ((((2u * ks + bSel) << 4) ^ ((uint32_t)(bRow & 7) << 4)));
            uint32_t b0, b1, b2, b3;
            LDMATRIX_X4(b0, b1, b2, b3, baddr);
            MMA_BF16(acc[nt2 * 2],     a0, a1, a2, a3, b0, b1);
            MMA_BF16(acc[nt2 * 2 + 1], a0, a1, a2, a3, b2, b3);
        }
    }

    // ------------------------------------------------------------------
    // Prefetch y_obs for the epilogue (hide DRAM latency behind fold+sync)
    // ------------------------------------------------------------------
    float4 yo[8];
#pragma unroll
    for (int it = 0; it < 8; ++it) {
        const int r = it * 8 + wid;
        const size_t base = ((size_t)(blockIdx.x * TILE + r)) * CC;
        yo[it] = ((const float4*)(x + base + 2 * DD))[lane];
    }

    // ------------------------------------------------------------------
    // Phase 3a: fold D = acc + V + mean back into Vs
    // ------------------------------------------------------------------
    {
        const int r1 = m0 + (lane >> 2);
        const int r2 = r1 + 8;
        const int cl = 2 * (lane & 3);
#pragma unroll
        for (int nt = 0; nt < 8; ++nt) {
            const int c = nb + nt * 8 + cl;
            const float m_c0 = Ms[c], m_c1 = Ms[c + 1];
            float* p1 = &Vs[r1 * 132 + c];
            float* p2 = &Vs[r2 * 132 + c];
            p1[0] = acc[nt][0] + p1[0] + m_c0;
            p1[1] = acc[nt][1] + p1[1] + m_c1;
            p2[0] = acc[nt][2] + p2[0] + m_c0;
            p2[1] = acc[nt][3] + p2[1] + m_c1;
        }
    }
    __syncthreads();

    // ------------------------------------------------------------------
    // Phase 3b: coalesced epilogue: smooth = D; y_trans = y_obs - smooth
    // ------------------------------------------------------------------
    {
        const int J = lane;
#pragma unroll
        for (int it = 0; it < 8; ++it) {
            const int r = it * 8 + wid;
            float4 d4 = *(const float4*)&Vs[r * 132 + J * 4];
            const size_t base = ((size_t)(blockIdx.x * TILE + r)) * CC;
            ((float4*)(out + base))[J] = d4;                      // smooth
            ((float4*)(out + base + 2 * DD))[J] =
                make_float4(yo[it].x - d4.x, yo[it].y - d4.y,
                            yo[it].z - d4.z, yo[it].w - d4.w);
        }
    }
}

// ---------------------------------------------------------------------------
extern "C" void kernel_launch(void* const* d_in, const int* in_sizes, int n_in,
                              void* d_out, int out_size) {
    const float* x    = (const float*)d_in[0];
    const float* kern = (const float*)d_in[1];
    float* out        = (float*)d_out;

    prep_kernel<<<BB * SEG + 128, 128>>>(x, kern);

    cudaFuncSetAttribute(crosschan_main_kernel,
                         cudaFuncAttributeMaxDynamicSharedMemorySize, S_TOTAL);
    crosschan_main_kernel<<<BB * (TT / TILE), 256, S_TOTAL>>>(x, out);
}

// round 5
// speedup vs baseline: 1.7474x; 1.0024x over previous
#include <cuda_runtime.h>
#include <cuda_bf16.h>
#include <cstdint>

#define BB 128
#define TT 1024
#define DD 128
#define CC 384
#define SEG 16
#define TSEG (TT/SEG)
#define TILE 64                   // rows per CTA

// ---- smem byte offsets ----
#define S_MS 0                    // 512 B mean
#define S_E  512                  // 32 KB E (bf16, swizzled); aliased by Dbuf (34816 B)
#define S_A  (S_E + 34816)        // 16 KB  Ahi = bf16(V)
#define S_AL (S_A + 16384)        // 16 KB  Alo = bf16(V - hi)
#define S_TOTAL (S_AL + 16384)    // 68096 B
#define DPAD 136                  // Dbuf row pitch in floats

// ---- device scratch (fully overwritten each launch -> deterministic) ----
__device__ float g_partial[BB * SEG * DD];
__device__ __align__(16) unsigned char g_E[32768];

// swizzled offset inside a [rows][128] bf16 tile with 256B rows
__device__ __forceinline__ uint32_t tile_off(int r, int k) {
    return (uint32_t)r * 256u + ((((uint32_t)k >> 3) ^ ((uint32_t)r & 7u)) << 4)
         + ((uint32_t)k & 7u) * 2u;
}

__device__ __forceinline__ uint32_t smem_u32(const void* p) {
    uint32_t a;
    asm("{ .reg .u64 t; cvta.to.shared.u64 t, %1; cvt.u32.u64 %0, t; }"
        : "=r"(a) : "l"(p));
    return a;
}

#define LDMATRIX_X4(r0, r1, r2, r3, addr)                                      \
    asm volatile("ldmatrix.sync.aligned.m8n8.x4.shared.b16 {%0,%1,%2,%3}, [%4];" \
        : "=r"(r0), "=r"(r1), "=r"(r2), "=r"(r3) : "r"(addr))

#define MMA_BF16(d, a0, a1, a2, a3, b0, b1)                                    \
    asm volatile("mma.sync.aligned.m16n8k16.row.col.f32.bf16.bf16.f32 "        \
        "{%0,%1,%2,%3}, {%4,%5,%6,%7}, {%8,%9}, {%0,%1,%2,%3};"                \
        : "+f"((d)[0]), "+f"((d)[1]), "+f"((d)[2]), "+f"((d)[3])               \
        : "r"(a0), "r"(a1), "r"(a2), "r"(a3), "r"(b0), "r"(b1))

#define CP_ASYNC16(saddr, gaddr)                                               \
    asm volatile("cp.async.cg.shared.global [%0], [%1], 16;"                   \
        :: "r"(saddr), "l"(gaddr) : "memory")
#define CP_COMMIT() asm volatile("cp.async.commit_group;" ::: "memory")
#define CP_WAIT0()  asm volatile("cp.async.wait_group 0;" ::: "memory")

__device__ __forceinline__ float2 bfx2f(uint32_t u) {
    return __bfloat1622float2(*reinterpret_cast<__nv_bfloat162*>(&u));
}

// ---------------------------------------------------------------------------
// Kernel A: fused prep. blocks [0,2048) = mean partials; [2048,2176) = E setup
// ---------------------------------------------------------------------------
__global__ void prep_kernel(const float* __restrict__ x,
                            const float* __restrict__ kern) {
    if (blockIdx.x < BB * SEG) {
        int bs = blockIdx.x;
        int b = bs / SEG, s = bs % SEG, d = threadIdx.x;
        const float* p = x + ((size_t)(b * TT + s * TSEG)) * CC + d;
        float acc = 0.f;
#pragma unroll 16
        for (int t = 0; t < TSEG; ++t) acc += p[(size_t)t * CC];
        g_partial[bs * DD + d] = acc;
    } else {
        int idx = (blockIdx.x - BB * SEG) * 128 + threadIdx.x;   // 16384
        int n = idx >> 7, k = idx & 127;
        float v = kern[k * DD + n] - (n == k ? 1.0f : 0.0f);
        *(__nv_bfloat16*)(g_E + tile_off(n, k)) = __float2bfloat16(v);
    }
}

// ---------------------------------------------------------------------------
// Kernel B: main fused kernel. grid = 2048 (64 rows each), block = 256.
// ---------------------------------------------------------------------------
__global__ __launch_bounds__(256, 3)
void crosschan_main_kernel(const float* __restrict__ x, float* __restrict__ out)
{
    extern __shared__ char smem[];
    const uint32_t sbase = smem_u32(smem);
    float* Ms = (float*)(smem + S_MS);
    float* Db = (float*)(smem + S_E);       // Dbuf aliases E after MMA
    const int tid  = threadIdx.x;
    const int wid  = tid >> 5;
    const int lane = tid & 31;
    const int b    = blockIdx.x >> 4;       // 16 tiles of 64 rows per batch

    // async E copy: issue now, wait after phase 1
    {
        const char* eg = (const char*)g_E;
#pragma unroll
        for (int i = 0; i < 8; ++i) {
            uint32_t off = (uint32_t)(tid + i * 256) * 16u;
            CP_ASYNC16(sbase + S_E + off, eg + off);
        }
        CP_COMMIT();
    }

    // mean reduce (128 threads)
    if (tid < DD) {
        float m = 0.f;
#pragma unroll
        for (int s = 0; s < SEG; ++s) m += g_partial[(b * SEG + s) * DD + tid];
        Ms[tid] = m * (1.0f / (float)TT);
    }
    __syncthreads();

    // ------------------------------------------------------------------
    // Phase 1: softmax + intensity + V as bf16 hi/lo tiles
    // 8 threads per row, 32 rows per pass, 2 passes.
    // ------------------------------------------------------------------
    {
        const int l = tid & 7;
#pragma unroll
        for (int pass = 0; pass < 2; ++pass) {
            const int r = pass * 32 + (tid >> 3);
            const size_t rowbase = ((size_t)(blockIdx.x * TILE + r)) * CC;
            const float4* xr = (const float4*)(x + rowbase);
            float4* o4 = (float4*)(out + rowbase);

            float4 w4[4], y4[4];
#pragma unroll
            for (int i = 0; i < 4; ++i) {
                y4[i] = xr[l * 4 + i];
                w4[i] = xr[32 + l * 4 + i];
            }
            float ex[16], s = 0.f;
#pragma unroll
            for (int i = 0; i < 4; ++i) {
                ex[4*i+0] = __expf(w4[i].x); ex[4*i+1] = __expf(w4[i].y);
                ex[4*i+2] = __expf(w4[i].z); ex[4*i+3] = __expf(w4[i].w);
                s += ex[4*i+0] + ex[4*i+1] + ex[4*i+2] + ex[4*i+3];
            }
            s += __shfl_xor_sync(0xffffffffu, s, 1);
            s += __shfl_xor_sync(0xffffffffu, s, 2);
            s += __shfl_xor_sync(0xffffffffu, s, 4);
            const float inv = 1.0f / s;

#pragma unroll
            for (int h = 0; h < 2; ++h) {        // two 8-wide chunks
                float v[8];
#pragma unroll
                for (int i = 0; i < 2; ++i) {
                    const int ii = h * 2 + i;
                    const int c0 = l * 16 + ii * 4;
                    float4 ev = make_float4(ex[4*ii+0], ex[4*ii+1],
                                            ex[4*ii+2], ex[4*ii+3]);
                    o4[32 + l * 4 + ii] = ev;    // intensity = exp(w)
                    v[4*i+0] = ev.x * inv * (y4[ii].x - Ms[c0 + 0]);
                    v[4*i+1] = ev.y * inv * (y4[ii].y - Ms[c0 + 1]);
                    v[4*i+2] = ev.z * inv * (y4[ii].z - Ms[c0 + 2]);
                    v[4*i+3] = ev.w * inv * (y4[ii].w - Ms[c0 + 3]);
                }
                uint32_t ph[4], pl[4];
#pragma unroll
                for (int j = 0; j < 4; ++j) {
                    float a = v[2*j], c = v[2*j+1];
                    __nv_bfloat162 th = __floats2bfloat162_rn(a, c);
                    float2 back = __bfloat1622float2(th);
                    __nv_bfloat162 tl = __floats2bfloat162_rn(a - back.x,
                                                              c - back.y);
                    ph[j] = *reinterpret_cast<uint32_t*>(&th);
                    pl[j] = *reinterpret_cast<uint32_t*>(&tl);
                }
                uint32_t off = tile_off(r, l * 16 + h * 8);
                *(uint4*)(smem + S_A  + off) = make_uint4(ph[0], ph[1], ph[2], ph[3]);
                *(uint4*)(smem + S_AL + off) = make_uint4(pl[0], pl[1], pl[2], pl[3]);
            }
        }
    }
    CP_WAIT0();
    __syncthreads();

    // ------------------------------------------------------------------
    // Phase 2: V@E via bf16 mma.sync. Warp w: rows m0..m0+15, cols nb..nb+63.
    // ------------------------------------------------------------------
    const int m0 = (wid >> 1) * 16;
    const int nb = (wid & 1) * 64;

    float acc[8][4];
#pragma unroll
    for (int i = 0; i < 8; ++i)
#pragma unroll
        for (int j = 0; j < 4; ++j) acc[i][j] = 0.f;

    const int aRow = m0 + (lane & 7) + (lane & 8);
    const uint32_t aBase = sbase + S_A + aRow * 256;
    const uint32_t aXor  = (uint32_t)(aRow & 7) << 4;
    const uint32_t aSel  = (uint32_t)(lane >> 4);
    const int bRowOff = (lane & 7) + ((lane >> 4) << 3);
    const uint32_t bSel = (uint32_t)((lane >> 3) & 1);

#pragma unroll
    for (int ks = 0; ks < 8; ++ks) {
        uint32_t a0, a1, a2, a3;
        LDMATRIX_X4(a0, a1, a2, a3,
                    aBase + ((((2u * ks + aSel) << 4) ^ aXor)));
#pragma unroll
        for (int nt2 = 0; nt2 < 4; ++nt2) {
            const int n0 = nb + nt2 * 16;
            const int bRow = n0 + bRowOff;
            uint32_t baddr = sbase + S_E + bRow * 256
                           + ((((2u * ks + bSel) << 4) ^ ((uint32_t)(bRow & 7) << 4)));
            uint32_t b0, b1, b2, b3;
            LDMATRIX_X4(b0, b1, b2, b3, baddr);
            MMA_BF16(acc[nt2 * 2],     a0, a1, a2, a3, b0, b1);
            MMA_BF16(acc[nt2 * 2 + 1], a0, a1, a2, a3, b2, b3);
        }
    }
    __syncthreads();   // all warps done reading E before Dbuf overwrites it

    // ------------------------------------------------------------------
    // Phase 3a: fold D = acc + (hi+lo) + mean into Dbuf (aliases E)
    // ------------------------------------------------------------------
    {
        const int r1 = m0 + (lane >> 2);
        const int r2 = r1 + 8;
        const int cl = 2 * (lane & 3);
#pragma unroll
        for (int nt = 0; nt < 8; ++nt) {
            const int c = nb + nt * 8 + cl;
            const float m0c = Ms[c], m1c = Ms[c + 1];
            uint32_t o1 = tile_off(r1, c), o2 = tile_off(r2, c);
            float2 h1 = bfx2f(*(uint32_t*)(smem + S_A  + o1));
            float2 l1 = bfx2f(*(uint32_t*)(smem + S_AL + o1));
            float2 h2 = bfx2f(*(uint32_t*)(smem + S_A  + o2));
            float2 l2 = bfx2f(*(uint32_t*)(smem + S_AL + o2));
            *(float2*)&Db[r1 * DPAD + c] =
                make_float2(acc[nt][0] + h1.x + l1.x + m0c,
                            acc[nt][1] + h1.y + l1.y + m1c);
            *(float2*)&Db[r2 * DPAD + c] =
                make_float2(acc[nt][2] + h2.x + l2.x + m0c,
                            acc[nt][3] + h2.y + l2.y + m1c);
        }
    }
    __syncthreads();

    // ------------------------------------------------------------------
    // Phase 3b: coalesced epilogue: smooth = D; y_trans = y_obs - smooth
    // ------------------------------------------------------------------
    {
        const int J = lane;
#pragma unroll
        for (int it = 0; it < 8; ++it) {
            const int r = it * 8 + wid;
            float4 d4 = *(const float4*)&Db[r * DPAD + J * 4];
            const size_t base = ((size_t)(blockIdx.x * TILE + r)) * CC;
            float4 yo = ((const float4*)(x + base + 2 * DD))[J];
            ((float4*)(out + base))[J] = d4;                      // smooth
            ((float4*)(out + base + 2 * DD))[J] =
                make_float4(yo.x - d4.x, yo.y - d4.y,
                            yo.z - d4.z, yo.w - d4.w);
        }
    }
}

// ---------------------------------------------------------------------------
extern "C" void kernel_launch(void* const* d_in, const int* in_sizes, int n_in,
                              void* d_out, int out_size) {
    const float* x    = (const float*)d_in[0];
    const float* kern = (const float*)d_in[1];
    float* out        = (float*)d_out;

    prep_kernel<<<BB * SEG + 128, 128>>>(x, kern);

    cudaFuncSetAttribute(crosschan_main_kernel,
                         cudaFuncAttributeMaxDynamicSharedMemorySize, S_TOTAL);
    crosschan_main_kernel<<<BB * (TT / TILE), 256, S_TOTAL>>>(x, out);
}

// round 6
// speedup vs baseline: 1.7490x; 1.0009x over previous
#include <cuda_runtime.h>
#include <cuda_bf16.h>
#include <cstdint>

#define BB 128
#define TT 1024
#define DD 128
#define CC 384
#define TILE 64                   // rows per work CTA
#define NE_BLK 64                 // E-setup CTAs

// ---- smem byte offsets ----
#define S_MS 0                    // 512 B mean
#define S_E  512                  // 32 KB E (bf16, swizzled); aliased by Dbuf + phaseA scratch
#define S_A  (S_E + 34816)        // 16 KB  Ahi = bf16(V)
#define S_AL (S_A + 16384)        // 16 KB  Alo = bf16(V - hi)
#define S_TOTAL (S_AL + 16384)    // 68096 B
#define DPAD 136                  // Dbuf row pitch in floats

// ---- device scratch (overwritten/reset every launch -> deterministic) ----
__device__ float g_partial[BB * 16 * DD];
__device__ __align__(16) unsigned char g_E[32768];
__device__ unsigned g_sync[256];  // [0..127] per-batch counters, [128] = E count

// swizzled offset inside a [rows][128] bf16 tile with 256B rows
__device__ __forceinline__ uint32_t tile_off(int r, int k) {
    return (uint32_t)r * 256u + ((((uint32_t)k >> 3) ^ ((uint32_t)r & 7u)) << 4)
         + ((uint32_t)k & 7u) * 2u;
}

__device__ __forceinline__ uint32_t smem_u32(const void* p) {
    uint32_t a;
    asm("{ .reg .u64 t; cvta.to.shared.u64 t, %1; cvt.u32.u64 %0, t; }"
        : "=r"(a) : "l"(p));
    return a;
}
__device__ __forceinline__ unsigned ld_acq(const unsigned* p) {
    unsigned v;
    asm volatile("ld.acquire.gpu.global.u32 %0, [%1];" : "=r"(v) : "l"(p) : "memory");
    return v;
}

#define LDMATRIX_X4(r0, r1, r2, r3, addr)                                      \
    asm volatile("ldmatrix.sync.aligned.m8n8.x4.shared.b16 {%0,%1,%2,%3}, [%4];" \
        : "=r"(r0), "=r"(r1), "=r"(r2), "=r"(r3) : "r"(addr))

#define MMA_BF16(d, a0, a1, a2, a3, b0, b1)                                    \
    asm volatile("mma.sync.aligned.m16n8k16.row.col.f32.bf16.bf16.f32 "        \
        "{%0,%1,%2,%3}, {%4,%5,%6,%7}, {%8,%9}, {%0,%1,%2,%3};"                \
        : "+f"((d)[0]), "+f"((d)[1]), "+f"((d)[2]), "+f"((d)[3])               \
        : "r"(a0), "r"(a1), "r"(a2), "r"(a3), "r"(b0), "r"(b1))

#define CP_ASYNC16(saddr, gaddr)                                               \
    asm volatile("cp.async.cg.shared.global [%0], [%1], 16;"                   \
        :: "r"(saddr), "l"(gaddr) : "memory")
#define CP_COMMIT() asm volatile("cp.async.commit_group;" ::: "memory")
#define CP_WAIT0()  asm volatile("cp.async.wait_group 0;" ::: "memory")

__device__ __forceinline__ float2 bfx2f(uint32_t u) {
    return __bfloat1622float2(*reinterpret_cast<__nv_bfloat162*>(&u));
}

// ---------------------------------------------------------------------------
// Single fused kernel. bids [0,64): E setup. bids [64, 64+2048): work CTAs.
// ---------------------------------------------------------------------------
__global__ __launch_bounds__(256, 3)
void crosschan_fused_kernel(const float* __restrict__ x,
                            const float* __restrict__ kern,
                            float* __restrict__ out)
{
    extern __shared__ char smem[];
    const uint32_t sbase = smem_u32(smem);
    const int tid  = threadIdx.x;

    // ------------------------- E setup CTAs --------------------------
    if (blockIdx.x < NE_BLK) {
        int idx = blockIdx.x * 256 + tid;          // 16384 elements
        int n = idx >> 7, k = idx & 127;
        float v = kern[k * DD + n] - (n == k ? 1.0f : 0.0f);
        *(__nv_bfloat16*)(g_E + tile_off(n, k)) = __float2bfloat16(v);
        __threadfence();
        __syncthreads();
        if (tid == 0) atomicAdd(&g_sync[128], 1u);
        return;
    }

    const int wb   = blockIdx.x - NE_BLK;          // work id 0..2047
    const int b    = wb >> 4;                      // batch
    const int wid  = tid >> 5;
    const int lane = tid & 31;
    float* Ms = (float*)(smem + S_MS);
    float* Db = (float*)(smem + S_E);              // Dbuf aliases E after MMA
    float* Pt = (float*)(smem + S_E);              // phase-A scratch (256 f)

    // ---------------- Phase A: partial column sums of y ----------------
    {
        const int d = tid & 127, half = tid >> 7;
        const float* p = x + ((size_t)(wb * TILE + half * 32)) * CC + d;
        float acc = 0.f;
#pragma unroll
        for (int t = 0; t < 32; ++t) acc += p[(size_t)t * CC];
        Pt[tid] = acc;
    }
    __syncthreads();
    if (tid < 128)
        g_partial[wb * DD + tid] = Pt[tid] + Pt[tid + 128];
    __threadfence();
    __syncthreads();
    if (tid == 0) atomicAdd(&g_sync[b], 1u);

    // ---------------- spin: batch partials + E ready ----------------
    if (tid == 0) {
        while (ld_acq(&g_sync[128]) < (unsigned)NE_BLK) __nanosleep(64);
        while (ld_acq(&g_sync[b]) < 16u) __nanosleep(64);
    }
    __syncthreads();

    // async E copy: issue now, wait after phase 1
    {
        const char* eg = (const char*)g_E;
#pragma unroll
        for (int i = 0; i < 8; ++i) {
            uint32_t off = (uint32_t)(tid + i * 256) * 16u;
            CP_ASYNC16(sbase + S_E + off, eg + off);
        }
        CP_COMMIT();
    }

    // mean reduce (128 threads, L2-hot partials)
    if (tid < DD) {
        float m = 0.f;
#pragma unroll
        for (int s = 0; s < 16; ++s) m += g_partial[(b * 16 + s) * DD + tid];
        Ms[tid] = m * (1.0f / (float)TT);
    }
    __syncthreads();

    // ------------------------------------------------------------------
    // Phase 1: softmax + intensity + V as bf16 hi/lo tiles (y re-read: L2)
    // ------------------------------------------------------------------
    {
        const int l = tid & 7;
#pragma unroll
        for (int pass = 0; pass < 2; ++pass) {
            const int r = pass * 32 + (tid >> 3);
            const size_t rowbase = ((size_t)(wb * TILE + r)) * CC;
            const float4* xr = (const float4*)(x + rowbase);
            float4* o4 = (float4*)(out + rowbase);

            float4 w4[4], y4[4];
#pragma unroll
            for (int i = 0; i < 4; ++i) {
                y4[i] = xr[l * 4 + i];
                w4[i] = xr[32 + l * 4 + i];
            }
            float ex[16], s = 0.f;
#pragma unroll
            for (int i = 0; i < 4; ++i) {
                ex[4*i+0] = __expf(w4[i].x); ex[4*i+1] = __expf(w4[i].y);
                ex[4*i+2] = __expf(w4[i].z); ex[4*i+3] = __expf(w4[i].w);
                s += ex[4*i+0] + ex[4*i+1] + ex[4*i+2] + ex[4*i+3];
            }
            s += __shfl_xor_sync(0xffffffffu, s, 1);
            s += __shfl_xor_sync(0xffffffffu, s, 2);
            s += __shfl_xor_sync(0xffffffffu, s, 4);
            const float inv = 1.0f / s;

#pragma unroll
            for (int h = 0; h < 2; ++h) {
                float v[8];
#pragma unroll
                for (int i = 0; i < 2; ++i) {
                    const int ii = h * 2 + i;
                    const int c0 = l * 16 + ii * 4;
                    float4 ev = make_float4(ex[4*ii+0], ex[4*ii+1],
                                            ex[4*ii+2], ex[4*ii+3]);
                    o4[32 + l * 4 + ii] = ev;    // intensity = exp(w)
                    v[4*i+0] = ev.x * inv * (y4[ii].x - Ms[c0 + 0]);
                    v[4*i+1] = ev.y * inv * (y4[ii].y - Ms[c0 + 1]);
                    v[4*i+2] = ev.z * inv * (y4[ii].z - Ms[c0 + 2]);
                    v[4*i+3] = ev.w * inv * (y4[ii].w - Ms[c0 + 3]);
                }
                uint32_t ph[4], pl[4];
#pragma unroll
                for (int j = 0; j < 4; ++j) {
                    float a = v[2*j], c = v[2*j+1];
                    __nv_bfloat162 th = __floats2bfloat162_rn(a, c);
                    float2 back = __bfloat1622float2(th);
                    __nv_bfloat162 tl = __floats2bfloat162_rn(a - back.x,
                                                              c - back.y);
                    ph[j] = *reinterpret_cast<uint32_t*>(&th);
                    pl[j] = *reinterpret_cast<uint32_t*>(&tl);
                }
                uint32_t off = tile_off(r, l * 16 + h * 8);
                *(uint4*)(smem + S_A  + off) = make_uint4(ph[0], ph[1], ph[2], ph[3]);
                *(uint4*)(smem + S_AL + off) = make_uint4(pl[0], pl[1], pl[2], pl[3]);
            }
        }
    }
    CP_WAIT0();
    __syncthreads();

    // ------------------------------------------------------------------
    // Phase 2: V@E via bf16 mma.sync
    // ------------------------------------------------------------------
    const int m0 = (wid >> 1) * 16;
    const int nb = (wid & 1) * 64;

    float acc[8][4];
#pragma unroll
    for (int i = 0; i < 8; ++i)
#pragma unroll
        for (int j = 0; j < 4; ++j) acc[i][j] = 0.f;

    const int aRow = m0 + (lane & 7) + (lane & 8);
    const uint32_t aBase = sbase + S_A + aRow * 256;
    const uint32_t aXor  = (uint32_t)(aRow & 7) << 4;
    const uint32_t aSel  = (uint32_t)(lane >> 4);
    const int bRowOff = (lane & 7) + ((lane >> 4) << 3);
    const uint32_t bSel = (uint32_t)((lane >> 3) & 1);

#pragma unroll
    for (int ks = 0; ks < 8; ++ks) {
        uint32_t a0, a1, a2, a3;
        LDMATRIX_X4(a0, a1, a2, a3,
                    aBase + ((((2u * ks + aSel) << 4) ^ aXor)));
#pragma unroll
        for (int nt2 = 0; nt2 < 4; ++nt2) {
            const int n0 = nb + nt2 * 16;
            const int bRow = n0 + bRowOff;
            uint32_t baddr = sbase + S_E + bRow * 256
                           + ((((2u * ks + bSel) << 4) ^ ((uint32_t)(bRow & 7) << 4)));
            uint32_t b0, b1, b2, b3;
            LDMATRIX_X4(b0, b1, b2, b3, baddr);
            MMA_BF16(acc[nt2 * 2],     a0, a1, a2, a3, b0, b1);
            MMA_BF16(acc[nt2 * 2 + 1], a0, a1, a2, a3, b2, b3);
        }
    }
    __syncthreads();   // all warps done reading E before Dbuf overwrites it

    // ------------------------------------------------------------------
    // Phase 3a: fold D = acc + (hi+lo) + mean into Dbuf (aliases E)
    // ------------------------------------------------------------------
    {
        const int r1 = m0 + (lane >> 2);
        const int r2 = r1 + 8;
        const int cl = 2 * (lane & 3);
#pragma unroll
        for (int nt = 0; nt < 8; ++nt) {
            const int c = nb + nt * 8 + cl;
            const float m0c = Ms[c], m1c = Ms[c + 1];
            uint32_t o1 = tile_off(r1, c), o2 = tile_off(r2, c);
            float2 h1 = bfx2f(*(uint32_t*)(smem + S_A  + o1));
            float2 l1 = bfx2f(*(uint32_t*)(smem + S_AL + o1));
            float2 h2 = bfx2f(*(uint32_t*)(smem + S_A  + o2));
            float2 l2 = bfx2f(*(uint32_t*)(smem + S_AL + o2));
            *(float2*)&Db[r1 * DPAD + c] =
                make_float2(acc[nt][0] + h1.x + l1.x + m0c,
                            acc[nt][1] + h1.y + l1.y + m1c);
            *(float2*)&Db[r2 * DPAD + c] =
                make_float2(acc[nt][2] + h2.x + l2.x + m0c,
                            acc[nt][3] + h2.y + l2.y + m1c);
        }
    }
    __syncthreads();

    // ------------------------------------------------------------------
    // Phase 3b: coalesced epilogue: smooth = D; y_trans = y_obs - smooth
    // ------------------------------------------------------------------
    {
        const int J = lane;
#pragma unroll
        for (int it = 0; it < 8; ++it) {
            const int r = it * 8 + wid;
            float4 d4 = *(const float4*)&Db[r * DPAD + J * 4];
            const size_t base = ((size_t)(wb * TILE + r)) * CC;
            float4 yo = ((const float4*)(x + base + 2 * DD))[J];
            ((float4*)(out + base))[J] = d4;                      // smooth
            ((float4*)(out + base + 2 * DD))[J] =
                make_float4(yo.x - d4.x, yo.y - d4.y,
                            yo.z - d4.z, yo.w - d4.w);
        }
    }
}

// ---------------------------------------------------------------------------
extern "C" void kernel_launch(void* const* d_in, const int* in_sizes, int n_in,
                              void* d_out, int out_size) {
    const float* x    = (const float*)d_in[0];
    const float* kern = (const float*)d_in[1];
    float* out        = (float*)d_out;

    void* syncp = nullptr;
    cudaGetSymbolAddress(&syncp, g_sync);
    cudaMemsetAsync(syncp, 0, 256 * sizeof(unsigned), 0);

    cudaFuncSetAttribute(crosschan_fused_kernel,
                         cudaFuncAttributeMaxDynamicSharedMemorySize, S_TOTAL);
    crosschan_fused_kernel<<<NE_BLK + BB * (TT / TILE), 256, S_TOTAL>>>(x, kern, out);
}